// round 2
// baseline (speedup 1.0000x reference)
#include <cuda_runtime.h>
#include <math.h>

#define NN 10000
#define DD 128

// Scratch (allocation-free rule: __device__ globals)
__device__ float g_agg[NN * DD];
__device__ float g_h1[NN * DD];
__device__ int   g_idx64;   // 1 if edge_index stored as int64, 0 if int32

// ---------------------------------------------------------------------------
// Detect edge_index element type on-device (graph-capturable, deterministic).
// If stored int64: values are small (< NN). If stored int32 but read as int64:
// value = lo + hi*2^32 with hi in [0,NN) -> huge with overwhelming probability.
// ---------------------------------------------------------------------------
__global__ void detect_idx_kernel(const void* ei_raw) {
    const long long* p = (const long long*)ei_raw;
    int ok64 = 1;
    for (int i = 0; i < 16; i++) {
        long long v = p[i];
        if (v < 0 || v >= NN) ok64 = 0;
    }
    g_idx64 = ok64;
}

// ---------------------------------------------------------------------------
// agg = x  (float4 copy; h = (1+eps)*x + agg with eps=0 -> init accumulator)
// ---------------------------------------------------------------------------
__global__ void copy_kernel(const float* __restrict__ in, float* __restrict__ out, int n4) {
    int i = blockIdx.x * blockDim.x + threadIdx.x;
    if (i < n4) ((float4*)out)[i] = ((const float4*)in)[i];
}

// ---------------------------------------------------------------------------
// Scatter-add: one warp per edge. Lane l handles columns [4l, 4l+4).
// Gather feat[src] row (512B, coalesced, L2-resident) then 4 atomicAdds
// (return unused -> ptxas emits REDG, no round trip).
// ---------------------------------------------------------------------------
__global__ void scatter_kernel(const float* __restrict__ feat,
                               const void* __restrict__ ei_raw,
                               float* __restrict__ agg, int E) {
    int warp = (blockIdx.x * blockDim.x + threadIdx.x) >> 5;
    int lane = threadIdx.x & 31;
    if (warp >= E) return;

    int s, d;
    if (g_idx64) {
        const long long* ei = (const long long*)ei_raw;
        s = (int)ei[warp];
        d = (int)ei[E + warp];
    } else {
        const int* ei = (const int*)ei_raw;
        s = ei[warp];
        d = ei[E + warp];
    }
    if ((unsigned)s >= NN || (unsigned)d >= NN) return;  // defensive

    float4 v = ((const float4*)(feat + (size_t)s * DD))[lane];
    float* dp = agg + (size_t)d * DD + lane * 4;
    atomicAdd(dp + 0, v.x);
    atomicAdd(dp + 1, v.y);
    atomicAdd(dp + 2, v.z);
    atomicAdd(dp + 3, v.w);
}

// ---------------------------------------------------------------------------
// MLP: out[n] = act( hin[n] @ W + b ).  W [128x128] staged in shared (64KB).
// blockDim = 128 (thread j owns output column j). 2 nodes per inner pass.
// MODE 0: ReLU.  MODE 1: log_softmax over the 128 columns.
// ---------------------------------------------------------------------------
template <int MODE>
__global__ void mlp_kernel(const float* __restrict__ hin,
                           const float* __restrict__ W,
                           const float* __restrict__ b,
                           float* __restrict__ out,
                           int nodes_per_block) {
    extern __shared__ float sm[];
    float* sW   = sm;              // 128*128
    float* srow = sm + DD * DD;    // 2*128
    __shared__ float sred[8];

    int j = threadIdx.x;  // 0..127

    for (int i = j; i < DD * DD / 4; i += blockDim.x)
        ((float4*)sW)[i] = ((const float4*)W)[i];
    float bj = b[j];
    __syncthreads();

    int base = blockIdx.x * nodes_per_block;
    for (int n0 = 0; n0 < nodes_per_block; n0 += 2) {
        int node0 = base + n0;
        int node1 = node0 + 1;
        bool v0 = node0 < NN, v1 = node1 < NN;   // uniform across block

        srow[j]      = v0 ? hin[(size_t)node0 * DD + j] : 0.f;
        srow[DD + j] = v1 ? hin[(size_t)node1 * DD + j] : 0.f;
        __syncthreads();

        float a0 = bj, a1 = bj;
#pragma unroll 8
        for (int k = 0; k < DD; k++) {
            float w = sW[k * DD + j];
            a0 = fmaf(srow[k], w, a0);
            a1 = fmaf(srow[DD + k], w, a1);
        }

        if (MODE == 0) {
            if (v0) out[(size_t)node0 * DD + j] = fmaxf(a0, 0.f);
            if (v1) out[(size_t)node1 * DD + j] = fmaxf(a1, 0.f);
        } else {
            float m0 = a0, m1 = a1;
#pragma unroll
            for (int o = 16; o; o >>= 1) {
                m0 = fmaxf(m0, __shfl_xor_sync(0xffffffffu, m0, o));
                m1 = fmaxf(m1, __shfl_xor_sync(0xffffffffu, m1, o));
            }
            int wid = j >> 5;
            if ((j & 31) == 0) { sred[wid] = m0; sred[4 + wid] = m1; }
            __syncthreads();
            m0 = fmaxf(fmaxf(sred[0], sred[1]), fmaxf(sred[2], sred[3]));
            m1 = fmaxf(fmaxf(sred[4], sred[5]), fmaxf(sred[6], sred[7]));

            float e0 = expf(a0 - m0), e1 = expf(a1 - m1);
            float s0 = e0, s1 = e1;
#pragma unroll
            for (int o = 16; o; o >>= 1) {
                s0 += __shfl_xor_sync(0xffffffffu, s0, o);
                s1 += __shfl_xor_sync(0xffffffffu, s1, o);
            }
            __syncthreads();  // protect sred reuse
            if ((j & 31) == 0) { sred[wid] = s0; sred[4 + wid] = s1; }
            __syncthreads();
            s0 = sred[0] + sred[1] + sred[2] + sred[3];
            s1 = sred[4] + sred[5] + sred[6] + sred[7];

            if (v0) out[(size_t)node0 * DD + j] = a0 - m0 - logf(s0);
            if (v1) out[(size_t)node1 * DD + j] = a1 - m1 - logf(s1);
        }
        __syncthreads();
    }
}

extern "C" void kernel_launch(void* const* d_in, const int* in_sizes, int n_in,
                              void* d_out, int out_size) {
    const float* x   = (const float*)d_in[0];
    const void*  ei  = d_in[1];
    const float* w1  = (const float*)d_in[2];
    const float* b1  = (const float*)d_in[3];
    const float* w2  = (const float*)d_in[4];
    const float* b2  = (const float*)d_in[5];
    float* out       = (float*)d_out;
    int E = in_sizes[1] / 2;

    float* agg = nullptr;
    float* h1  = nullptr;
    cudaGetSymbolAddress((void**)&agg, g_agg);
    cudaGetSymbolAddress((void**)&h1,  g_h1);

    const int SMEM = (DD * DD + 2 * DD) * (int)sizeof(float);  // 66560 B
    cudaFuncSetAttribute(mlp_kernel<0>, cudaFuncAttributeMaxDynamicSharedMemorySize, SMEM);
    cudaFuncSetAttribute(mlp_kernel<1>, cudaFuncAttributeMaxDynamicSharedMemorySize, SMEM);

    const int n4 = NN * DD / 4;
    const int copy_blocks = (n4 + 255) / 256;
    const int scat_blocks = (int)(((long long)E * 32 + 255) / 256);
    const int NPB = 8;
    const int mlp_blocks = (NN + NPB - 1) / NPB;

    detect_idx_kernel<<<1, 1>>>(ei);

    // ---- layer 1 ----
    copy_kernel<<<copy_blocks, 256>>>(x, agg, n4);
    scatter_kernel<<<scat_blocks, 256>>>(x, ei, agg, E);
    mlp_kernel<0><<<mlp_blocks, 128, SMEM>>>(agg, w1, b1, h1, NPB);

    // ---- layer 2 ----
    copy_kernel<<<copy_blocks, 256>>>(h1, agg, n4);
    scatter_kernel<<<scat_blocks, 256>>>(h1, ei, agg, E);
    mlp_kernel<1><<<mlp_blocks, 128, SMEM>>>(agg, w2, b2, out, NPB);
}

// round 3
// speedup vs baseline: 2.7296x; 2.7296x over previous
#include <cuda_runtime.h>
#include <math.h>

#define NN 10000
#define DD 128
#define EMAX 640000

// Scratch (allocation-free rule: __device__ globals)
__device__ float g_agg[NN * DD];
__device__ float g_h1[NN * DD];
__device__ int   g_deg[NN];
__device__ int   g_off[NN + 1];
__device__ int   g_cursor[NN];
__device__ int   g_bin[EMAX];
__device__ int   g_idx64;   // 1 if edge_index stored as int64, 0 if int32

// ---------------------------------------------------------------------------
// Detect edge_index element type on-device (graph-capturable, deterministic).
// ---------------------------------------------------------------------------
__global__ void detect_idx_kernel(const void* ei_raw) {
    const long long* p = (const long long*)ei_raw;
    int ok64 = 1;
    for (int i = 0; i < 16; i++) {
        long long v = p[i];
        if (v < 0 || v >= NN) ok64 = 0;
    }
    g_idx64 = ok64;
}

__global__ void zero_deg_kernel() {
    int i = blockIdx.x * blockDim.x + threadIdx.x;
    if (i < NN) g_deg[i] = 0;
}

__device__ __forceinline__ int load_idx(const void* ei_raw, long long pos) {
    if (g_idx64) return (int)((const long long*)ei_raw)[pos];
    return ((const int*)ei_raw)[pos];
}

// Histogram of destination degrees.
__global__ void hist_kernel(const void* __restrict__ ei_raw, int E) {
    int i = blockIdx.x * blockDim.x + threadIdx.x;
    if (i >= E) return;
    int d = load_idx(ei_raw, (long long)E + i);
    if ((unsigned)d < NN) atomicAdd(&g_deg[d], 1);
}

// Single-block exclusive scan over deg -> off, cursor.
__global__ void scan_kernel() {
    __shared__ int s[1024];
    __shared__ int carry;
    if (threadIdx.x == 0) carry = 0;
    __syncthreads();
    for (int base = 0; base < NN; base += 1024) {
        int i = base + threadIdx.x;
        int v = (i < NN) ? g_deg[i] : 0;
        s[threadIdx.x] = v;
        __syncthreads();
        for (int o = 1; o < 1024; o <<= 1) {
            int t = (threadIdx.x >= o) ? s[threadIdx.x - o] : 0;
            __syncthreads();
            s[threadIdx.x] += t;
            __syncthreads();
        }
        int excl = s[threadIdx.x] - v;
        if (i < NN) { g_off[i] = carry + excl; g_cursor[i] = carry + excl; }
        __syncthreads();
        if (threadIdx.x == 1023) carry += s[1023];
        __syncthreads();
    }
    if (threadIdx.x == 0) g_off[NN] = carry;
}

// Fill bins: bin[pos] = src for each edge grouped by dst.
__global__ void fill_kernel(const void* __restrict__ ei_raw, int E) {
    int i = blockIdx.x * blockDim.x + threadIdx.x;
    if (i >= E) return;
    int s = load_idx(ei_raw, i);
    int d = load_idx(ei_raw, (long long)E + i);
    if ((unsigned)s >= NN || (unsigned)d >= NN) return;
    int pos = atomicAdd(&g_cursor[d], 1);
    g_bin[pos] = s;
}

// ---------------------------------------------------------------------------
// Gather-aggregate: block per node (128 threads, thread j = column j).
// agg[n][j] = feat[n][j] + sum over in-edges feat[src][j]   (eps = 0)
// ---------------------------------------------------------------------------
__global__ void agg_gather_kernel(const float* __restrict__ feat,
                                  float* __restrict__ agg) {
    int node = blockIdx.x;
    int j = threadIdx.x;
    __shared__ int sidx[128];

    int beg = g_off[node], end = g_off[node + 1];
    float acc = feat[(size_t)node * DD + j];   // self term
    float a0 = 0.f, a1 = 0.f, a2 = 0.f, a3 = 0.f;

    for (int base = beg; base < end; base += 128) {
        int cnt = min(128, end - base);
        if (j < cnt) sidx[j] = g_bin[base + j];
        __syncthreads();
        int t = 0;
        for (; t + 4 <= cnt; t += 4) {
            a0 += feat[(size_t)sidx[t + 0] * DD + j];
            a1 += feat[(size_t)sidx[t + 1] * DD + j];
            a2 += feat[(size_t)sidx[t + 2] * DD + j];
            a3 += feat[(size_t)sidx[t + 3] * DD + j];
        }
        for (; t < cnt; t++)
            a0 += feat[(size_t)sidx[t] * DD + j];
        __syncthreads();
    }
    agg[(size_t)node * DD + j] = acc + (a0 + a1) + (a2 + a3);
}

// ---------------------------------------------------------------------------
// MLP: out[n] = act( hin[n] @ W + b ).  W staged in shared, 4 nodes per pass.
// MODE 0: ReLU.  MODE 1: log_softmax over the 128 columns.
// ---------------------------------------------------------------------------
#define NPB 16

template <int MODE>
__global__ void mlp_kernel(const float* __restrict__ hin,
                           const float* __restrict__ W,
                           const float* __restrict__ b,
                           float* __restrict__ out) {
    extern __shared__ float sm[];
    float* sW   = sm;              // 128*128
    float* srow = sm + DD * DD;    // 4*128
    __shared__ float sred[16];

    int j = threadIdx.x;  // 0..127
    int lane = j & 31, wid = j >> 5;

    for (int i = j; i < DD * DD / 4; i += blockDim.x)
        ((float4*)sW)[i] = ((const float4*)W)[i];
    float bj = b[j];
    __syncthreads();

    int base = blockIdx.x * NPB;
    for (int n0 = 0; n0 < NPB; n0 += 4) {
        int node = base + n0;
#pragma unroll
        for (int t = 0; t < 4; t++) {
            int n = node + t;
            srow[t * DD + j] = (n < NN) ? hin[(size_t)n * DD + j] : 0.f;
        }
        __syncthreads();

        float a0 = bj, a1 = bj, a2 = bj, a3 = bj;
#pragma unroll 8
        for (int k = 0; k < DD; k += 4) {
            float4 r0 = *(const float4*)&srow[0 * DD + k];
            float4 r1 = *(const float4*)&srow[1 * DD + k];
            float4 r2 = *(const float4*)&srow[2 * DD + k];
            float4 r3 = *(const float4*)&srow[3 * DD + k];
            float w0 = sW[(k + 0) * DD + j];
            float w1 = sW[(k + 1) * DD + j];
            float w2 = sW[(k + 2) * DD + j];
            float w3 = sW[(k + 3) * DD + j];
            a0 = fmaf(r0.x, w0, a0); a0 = fmaf(r0.y, w1, a0);
            a0 = fmaf(r0.z, w2, a0); a0 = fmaf(r0.w, w3, a0);
            a1 = fmaf(r1.x, w0, a1); a1 = fmaf(r1.y, w1, a1);
            a1 = fmaf(r1.z, w2, a1); a1 = fmaf(r1.w, w3, a1);
            a2 = fmaf(r2.x, w0, a2); a2 = fmaf(r2.y, w1, a2);
            a2 = fmaf(r2.z, w2, a2); a2 = fmaf(r2.w, w3, a2);
            a3 = fmaf(r3.x, w0, a3); a3 = fmaf(r3.y, w1, a3);
            a3 = fmaf(r3.z, w2, a3); a3 = fmaf(r3.w, w3, a3);
        }

        float av[4] = {a0, a1, a2, a3};
        if (MODE == 0) {
#pragma unroll
            for (int t = 0; t < 4; t++) {
                int n = node + t;
                if (n < NN) out[(size_t)n * DD + j] = fmaxf(av[t], 0.f);
            }
        } else {
            float m[4], s[4];
#pragma unroll
            for (int t = 0; t < 4; t++) {
                float mm = av[t];
#pragma unroll
                for (int o = 16; o; o >>= 1)
                    mm = fmaxf(mm, __shfl_xor_sync(0xffffffffu, mm, o));
                if (lane == 0) sred[t * 4 + wid] = mm;
            }
            __syncthreads();
#pragma unroll
            for (int t = 0; t < 4; t++)
                m[t] = fmaxf(fmaxf(sred[t * 4 + 0], sred[t * 4 + 1]),
                             fmaxf(sred[t * 4 + 2], sred[t * 4 + 3]));
            __syncthreads();
#pragma unroll
            for (int t = 0; t < 4; t++) {
                float ss = expf(av[t] - m[t]);
#pragma unroll
                for (int o = 16; o; o >>= 1)
                    ss += __shfl_xor_sync(0xffffffffu, ss, o);
                if (lane == 0) sred[t * 4 + wid] = ss;
            }
            __syncthreads();
#pragma unroll
            for (int t = 0; t < 4; t++)
                s[t] = (sred[t * 4 + 0] + sred[t * 4 + 1]) +
                       (sred[t * 4 + 2] + sred[t * 4 + 3]);
#pragma unroll
            for (int t = 0; t < 4; t++) {
                int n = node + t;
                if (n < NN) out[(size_t)n * DD + j] = av[t] - m[t] - logf(s[t]);
            }
        }
        __syncthreads();
    }
}

extern "C" void kernel_launch(void* const* d_in, const int* in_sizes, int n_in,
                              void* d_out, int out_size) {
    const float* x   = (const float*)d_in[0];
    const void*  ei  = d_in[1];
    const float* w1  = (const float*)d_in[2];
    const float* b1  = (const float*)d_in[3];
    const float* w2  = (const float*)d_in[4];
    const float* b2  = (const float*)d_in[5];
    float* out       = (float*)d_out;
    int E = in_sizes[1] / 2;
    if (E > EMAX) E = EMAX;

    float* agg = nullptr;
    float* h1  = nullptr;
    cudaGetSymbolAddress((void**)&agg, g_agg);
    cudaGetSymbolAddress((void**)&h1,  g_h1);

    const int SMEM = (DD * DD + 4 * DD) * (int)sizeof(float);  // 67584 B
    cudaFuncSetAttribute(mlp_kernel<0>, cudaFuncAttributeMaxDynamicSharedMemorySize, SMEM);
    cudaFuncSetAttribute(mlp_kernel<1>, cudaFuncAttributeMaxDynamicSharedMemorySize, SMEM);

    const int eb = (E + 255) / 256;
    const int mlp_blocks = (NN + NPB - 1) / NPB;

    // ---- CSR build (once, reused by both layers) ----
    detect_idx_kernel<<<1, 1>>>(ei);
    zero_deg_kernel<<<(NN + 255) / 256, 256>>>();
    hist_kernel<<<eb, 256>>>(ei, E);
    scan_kernel<<<1, 1024>>>();
    fill_kernel<<<eb, 256>>>(ei, E);

    // ---- layer 1 ----
    agg_gather_kernel<<<NN, 128>>>(x, agg);
    mlp_kernel<0><<<mlp_blocks, 128, SMEM>>>(agg, w1, b1, h1);

    // ---- layer 2 ----
    agg_gather_kernel<<<NN, 128>>>(h1, agg);
    mlp_kernel<1><<<mlp_blocks, 128, SMEM>>>(agg, w2, b2, out);
}

// round 4
// speedup vs baseline: 2.8041x; 1.0273x over previous
#include <cuda_runtime.h>
#include <math.h>

#define NN 10000
#define DD 128
#define EMAX 640000

// Scratch (allocation-free rule: __device__ globals)
__device__ float g_agg[NN * DD];
__device__ float g_h1[NN * DD];
__device__ int   g_deg[NN];
__device__ int   g_off[NN + 1];
__device__ int   g_cursor[NN];
__device__ int   g_bin[EMAX];
__device__ int   g_idx64;   // 1 if edge_index stored as int64, 0 if int32

// ---------------------------------------------------------------------------
// Fused: zero degree array + detect edge_index element type (block 0 thread 0).
// int64 detection: real int64 values are < NN; int32 data misread as int64
// gives huge values with overwhelming probability.
// ---------------------------------------------------------------------------
__global__ void init_kernel(const void* ei_raw) {
    int i = blockIdx.x * blockDim.x + threadIdx.x;
    if (i < NN) g_deg[i] = 0;
    if (i == 0) {
        const long long* p = (const long long*)ei_raw;
        int ok64 = 1;
        for (int k = 0; k < 16; k++) {
            long long v = p[k];
            if (v < 0 || v >= NN) ok64 = 0;
        }
        g_idx64 = ok64;
    }
}

__device__ __forceinline__ int load_idx(const void* ei_raw, long long pos) {
    if (g_idx64) return (int)((const long long*)ei_raw)[pos];
    return ((const int*)ei_raw)[pos];
}

// Histogram of destination degrees.
__global__ void hist_kernel(const void* __restrict__ ei_raw, int E) {
    int i = blockIdx.x * blockDim.x + threadIdx.x;
    if (i >= E) return;
    int d = load_idx(ei_raw, (long long)E + i);
    if ((unsigned)d < NN) atomicAdd(&g_deg[d], 1);
}

// ---------------------------------------------------------------------------
// Single-block hierarchical exclusive scan: 1024 threads x 10-element segments.
// Segment-serial sums -> warp shfl scan -> 32 warp totals via smem -> write.
// 2 __syncthreads total.
// ---------------------------------------------------------------------------
#define SCAN_CH 10   // 1024 * 10 = 10240 >= NN

__global__ void scan_kernel() {
    __shared__ int swarp[32];
    int t = threadIdx.x;
    int lane = t & 31, wid = t >> 5;
    int base_i = t * SCAN_CH;

    // serial segment sum
    int seg[SCAN_CH];
    int ssum = 0;
#pragma unroll
    for (int k = 0; k < SCAN_CH; k++) {
        int i = base_i + k;
        int v = (i < NN) ? g_deg[i] : 0;
        seg[k] = v;
        ssum += v;
    }

    // warp inclusive scan of segment sums
    int incl = ssum;
#pragma unroll
    for (int o = 1; o < 32; o <<= 1) {
        int u = __shfl_up_sync(0xffffffffu, incl, o);
        if (lane >= o) incl += u;
    }
    if (lane == 31) swarp[wid] = incl;
    __syncthreads();

    // warp 0 scans the 32 warp totals
    if (wid == 0) {
        int w = swarp[lane];
        int wi = w;
#pragma unroll
        for (int o = 1; o < 32; o <<= 1) {
            int u = __shfl_up_sync(0xffffffffu, wi, o);
            if (lane >= o) wi += u;
        }
        swarp[lane] = wi - w;   // exclusive warp base
    }
    __syncthreads();

    int baseval = swarp[wid] + (incl - ssum);   // exclusive prefix of this segment

    // write per-element exclusive prefixes
    int run = baseval;
#pragma unroll
    for (int k = 0; k < SCAN_CH; k++) {
        int i = base_i + k;
        if (i < NN) { g_off[i] = run; g_cursor[i] = run; }
        run += seg[k];
    }
    if (t == 1023) g_off[NN] = run;   // grand total (tail elements are 0)
}

// Fill bins: bin[pos] = src for each edge grouped by dst.
__global__ void fill_kernel(const void* __restrict__ ei_raw, int E) {
    int i = blockIdx.x * blockDim.x + threadIdx.x;
    if (i >= E) return;
    int s = load_idx(ei_raw, i);
    int d = load_idx(ei_raw, (long long)E + i);
    if ((unsigned)s >= NN || (unsigned)d >= NN) return;
    int pos = atomicAdd(&g_cursor[d], 1);
    g_bin[pos] = s;
}

// ---------------------------------------------------------------------------
// Gather-aggregate: block per node (128 threads, thread j = column j).
// agg[n][j] = feat[n][j] + sum over in-edges feat[src][j]   (eps = 0)
// ---------------------------------------------------------------------------
__global__ void agg_gather_kernel(const float* __restrict__ feat,
                                  float* __restrict__ agg) {
    int node = blockIdx.x;
    int j = threadIdx.x;
    __shared__ int sidx[128];

    int beg = g_off[node], end = g_off[node + 1];
    float acc = feat[(size_t)node * DD + j];   // self term
    float a0 = 0.f, a1 = 0.f, a2 = 0.f, a3 = 0.f;

    for (int base = beg; base < end; base += 128) {
        int cnt = min(128, end - base);
        if (j < cnt) sidx[j] = g_bin[base + j];
        __syncthreads();
        int t = 0;
        for (; t + 4 <= cnt; t += 4) {
            a0 += feat[(size_t)sidx[t + 0] * DD + j];
            a1 += feat[(size_t)sidx[t + 1] * DD + j];
            a2 += feat[(size_t)sidx[t + 2] * DD + j];
            a3 += feat[(size_t)sidx[t + 3] * DD + j];
        }
        for (; t < cnt; t++)
            a0 += feat[(size_t)sidx[t] * DD + j];
        __syncthreads();
    }
    agg[(size_t)node * DD + j] = acc + (a0 + a1) + (a2 + a3);
}

// ---------------------------------------------------------------------------
// MLP: out[n] = act( hin[n] @ W + b ).  W staged in shared, 4 nodes per pass.
// MODE 0: ReLU.  MODE 1: log_softmax over the 128 columns.
// ---------------------------------------------------------------------------
#define NPB 16

template <int MODE>
__global__ void mlp_kernel(const float* __restrict__ hin,
                           const float* __restrict__ W,
                           const float* __restrict__ b,
                           float* __restrict__ out) {
    extern __shared__ float sm[];
    float* sW   = sm;              // 128*128
    float* srow = sm + DD * DD;    // 4*128
    __shared__ float sred[16];

    int j = threadIdx.x;  // 0..127
    int lane = j & 31, wid = j >> 5;

    for (int i = j; i < DD * DD / 4; i += blockDim.x)
        ((float4*)sW)[i] = ((const float4*)W)[i];
    float bj = b[j];
    __syncthreads();

    int base = blockIdx.x * NPB;
    for (int n0 = 0; n0 < NPB; n0 += 4) {
        int node = base + n0;
#pragma unroll
        for (int t = 0; t < 4; t++) {
            int n = node + t;
            srow[t * DD + j] = (n < NN) ? hin[(size_t)n * DD + j] : 0.f;
        }
        __syncthreads();

        float a0 = bj, a1 = bj, a2 = bj, a3 = bj;
#pragma unroll 8
        for (int k = 0; k < DD; k += 4) {
            float4 r0 = *(const float4*)&srow[0 * DD + k];
            float4 r1 = *(const float4*)&srow[1 * DD + k];
            float4 r2 = *(const float4*)&srow[2 * DD + k];
            float4 r3 = *(const float4*)&srow[3 * DD + k];
            float w0 = sW[(k + 0) * DD + j];
            float w1 = sW[(k + 1) * DD + j];
            float w2 = sW[(k + 2) * DD + j];
            float w3 = sW[(k + 3) * DD + j];
            a0 = fmaf(r0.x, w0, a0); a0 = fmaf(r0.y, w1, a0);
            a0 = fmaf(r0.z, w2, a0); a0 = fmaf(r0.w, w3, a0);
            a1 = fmaf(r1.x, w0, a1); a1 = fmaf(r1.y, w1, a1);
            a1 = fmaf(r1.z, w2, a1); a1 = fmaf(r1.w, w3, a1);
            a2 = fmaf(r2.x, w0, a2); a2 = fmaf(r2.y, w1, a2);
            a2 = fmaf(r2.z, w2, a2); a2 = fmaf(r2.w, w3, a2);
            a3 = fmaf(r3.x, w0, a3); a3 = fmaf(r3.y, w1, a3);
            a3 = fmaf(r3.z, w2, a3); a3 = fmaf(r3.w, w3, a3);
        }

        float av[4] = {a0, a1, a2, a3};
        if (MODE == 0) {
#pragma unroll
            for (int t = 0; t < 4; t++) {
                int n = node + t;
                if (n < NN) out[(size_t)n * DD + j] = fmaxf(av[t], 0.f);
            }
        } else {
            float m[4], s[4];
#pragma unroll
            for (int t = 0; t < 4; t++) {
                float mm = av[t];
#pragma unroll
                for (int o = 16; o; o >>= 1)
                    mm = fmaxf(mm, __shfl_xor_sync(0xffffffffu, mm, o));
                if (lane == 0) sred[t * 4 + wid] = mm;
            }
            __syncthreads();
#pragma unroll
            for (int t = 0; t < 4; t++)
                m[t] = fmaxf(fmaxf(sred[t * 4 + 0], sred[t * 4 + 1]),
                             fmaxf(sred[t * 4 + 2], sred[t * 4 + 3]));
            __syncthreads();
#pragma unroll
            for (int t = 0; t < 4; t++) {
                float ss = expf(av[t] - m[t]);
#pragma unroll
                for (int o = 16; o; o >>= 1)
                    ss += __shfl_xor_sync(0xffffffffu, ss, o);
                if (lane == 0) sred[t * 4 + wid] = ss;
            }
            __syncthreads();
#pragma unroll
            for (int t = 0; t < 4; t++)
                s[t] = (sred[t * 4 + 0] + sred[t * 4 + 1]) +
                       (sred[t * 4 + 2] + sred[t * 4 + 3]);
#pragma unroll
            for (int t = 0; t < 4; t++) {
                int n = node + t;
                if (n < NN) out[(size_t)n * DD + j] = av[t] - m[t] - logf(s[t]);
            }
        }
        __syncthreads();
    }
}

extern "C" void kernel_launch(void* const* d_in, const int* in_sizes, int n_in,
                              void* d_out, int out_size) {
    const float* x   = (const float*)d_in[0];
    const void*  ei  = d_in[1];
    const float* w1  = (const float*)d_in[2];
    const float* b1  = (const float*)d_in[3];
    const float* w2  = (const float*)d_in[4];
    const float* b2  = (const float*)d_in[5];
    float* out       = (float*)d_out;
    int E = in_sizes[1] / 2;
    if (E > EMAX) E = EMAX;

    float* agg = nullptr;
    float* h1  = nullptr;
    cudaGetSymbolAddress((void**)&agg, g_agg);
    cudaGetSymbolAddress((void**)&h1,  g_h1);

    const int SMEM = (DD * DD + 4 * DD) * (int)sizeof(float);  // 67584 B
    cudaFuncSetAttribute(mlp_kernel<0>, cudaFuncAttributeMaxDynamicSharedMemorySize, SMEM);
    cudaFuncSetAttribute(mlp_kernel<1>, cudaFuncAttributeMaxDynamicSharedMemorySize, SMEM);

    const int eb = (E + 255) / 256;
    const int mlp_blocks = (NN + NPB - 1) / NPB;

    // ---- CSR build (once, reused by both layers) ----
    init_kernel<<<(NN + 255) / 256, 256>>>(ei);
    hist_kernel<<<eb, 256>>>(ei, E);
    scan_kernel<<<1, 1024>>>();
    fill_kernel<<<eb, 256>>>(ei, E);

    // ---- layer 1 ----
    agg_gather_kernel<<<NN, 128>>>(x, agg);
    mlp_kernel<0><<<mlp_blocks, 128, SMEM>>>(agg, w1, b1, h1);

    // ---- layer 2 ----
    agg_gather_kernel<<<NN, 128>>>(h1, agg);
    mlp_kernel<1><<<mlp_blocks, 128, SMEM>>>(agg, w2, b2, out);
}

// round 5
// speedup vs baseline: 2.9291x; 1.0446x over previous
#include <cuda_runtime.h>
#include <math.h>

#define NN 10000
#define DD 128
#define EMAX 640000

// Scratch (allocation-free rule: __device__ globals)
__device__ float g_agg[NN * DD];
__device__ float g_h1[NN * DD];
__device__ int   g_deg[NN];
__device__ int   g_off[NN + 1];
__device__ int   g_cursor[NN];
__device__ int   g_bin[EMAX];
__device__ int   g_idx64;   // 1 if edge_index stored as int64, 0 if int32

// ---------------------------------------------------------------------------
// Fused: zero degree array + detect edge_index element type.
// ---------------------------------------------------------------------------
__global__ void init_kernel(const void* ei_raw) {
    int i = blockIdx.x * blockDim.x + threadIdx.x;
    if (i < NN) g_deg[i] = 0;
    if (i == 0) {
        const long long* p = (const long long*)ei_raw;
        int ok64 = 1;
        for (int k = 0; k < 16; k++) {
            long long v = p[k];
            if (v < 0 || v >= NN) ok64 = 0;
        }
        g_idx64 = ok64;
    }
}

__device__ __forceinline__ int load_idx(const void* ei_raw, long long pos) {
    if (g_idx64) return (int)((const long long*)ei_raw)[pos];
    return ((const int*)ei_raw)[pos];
}

// ---------------------------------------------------------------------------
// Histogram of destination degrees — 4 edges per thread (independent chains).
// ---------------------------------------------------------------------------
__global__ void hist_kernel(const void* __restrict__ ei_raw, int E) {
    int base = (blockIdx.x * blockDim.x + threadIdx.x) * 4;
    if (base >= E) return;
    int d[4];
    int n = min(4, E - base);
#pragma unroll
    for (int k = 0; k < 4; k++)
        if (k < n) d[k] = load_idx(ei_raw, (long long)E + base + k);
#pragma unroll
    for (int k = 0; k < 4; k++)
        if (k < n && (unsigned)d[k] < NN) atomicAdd(&g_deg[d[k]], 1);
}

// ---------------------------------------------------------------------------
// Single-block hierarchical exclusive scan (1024 thr x 10-elt segments).
// ---------------------------------------------------------------------------
#define SCAN_CH 10   // 1024 * 10 = 10240 >= NN

__global__ void scan_kernel() {
    __shared__ int swarp[32];
    int t = threadIdx.x;
    int lane = t & 31, wid = t >> 5;
    int base_i = t * SCAN_CH;

    int seg[SCAN_CH];
    int ssum = 0;
#pragma unroll
    for (int k = 0; k < SCAN_CH; k++) {
        int i = base_i + k;
        int v = (i < NN) ? g_deg[i] : 0;
        seg[k] = v;
        ssum += v;
    }

    int incl = ssum;
#pragma unroll
    for (int o = 1; o < 32; o <<= 1) {
        int u = __shfl_up_sync(0xffffffffu, incl, o);
        if (lane >= o) incl += u;
    }
    if (lane == 31) swarp[wid] = incl;
    __syncthreads();

    if (wid == 0) {
        int w = swarp[lane];
        int wi = w;
#pragma unroll
        for (int o = 1; o < 32; o <<= 1) {
            int u = __shfl_up_sync(0xffffffffu, wi, o);
            if (lane >= o) wi += u;
        }
        swarp[lane] = wi - w;
    }
    __syncthreads();

    int run = swarp[wid] + (incl - ssum);
#pragma unroll
    for (int k = 0; k < SCAN_CH; k++) {
        int i = base_i + k;
        if (i < NN) { g_off[i] = run; g_cursor[i] = run; }
        run += seg[k];
    }
    if (t == 1023) g_off[NN] = run;
}

// ---------------------------------------------------------------------------
// Fill bins — 4 edges per thread (4 independent load->atomic->store chains).
// ---------------------------------------------------------------------------
__global__ void fill_kernel(const void* __restrict__ ei_raw, int E) {
    int base = (blockIdx.x * blockDim.x + threadIdx.x) * 4;
    if (base >= E) return;
    int n = min(4, E - base);
    int s[4], d[4];
#pragma unroll
    for (int k = 0; k < 4; k++)
        if (k < n) {
            s[k] = load_idx(ei_raw, base + k);
            d[k] = load_idx(ei_raw, (long long)E + base + k);
        }
#pragma unroll
    for (int k = 0; k < 4; k++)
        if (k < n && (unsigned)s[k] < NN && (unsigned)d[k] < NN) {
            int pos = atomicAdd(&g_cursor[d[k]], 1);
            g_bin[pos] = s[k];
        }
}

// ---------------------------------------------------------------------------
// Gather-aggregate: block per node (128 threads, thread j = column j).
// At the LTS throughput cap — structure protected.
// ---------------------------------------------------------------------------
__global__ void agg_gather_kernel(const float* __restrict__ feat,
                                  float* __restrict__ agg) {
    int node = blockIdx.x;
    int j = threadIdx.x;
    __shared__ int sidx[128];

    int beg = g_off[node], end = g_off[node + 1];
    float acc = feat[(size_t)node * DD + j];   // self term (eps = 0)
    float a0 = 0.f, a1 = 0.f, a2 = 0.f, a3 = 0.f;

    for (int base = beg; base < end; base += 128) {
        int cnt = min(128, end - base);
        if (j < cnt) sidx[j] = g_bin[base + j];
        __syncthreads();
        int t = 0;
        for (; t + 4 <= cnt; t += 4) {
            a0 += feat[(size_t)sidx[t + 0] * DD + j];
            a1 += feat[(size_t)sidx[t + 1] * DD + j];
            a2 += feat[(size_t)sidx[t + 2] * DD + j];
            a3 += feat[(size_t)sidx[t + 3] * DD + j];
        }
        for (; t < cnt; t++)
            a0 += feat[(size_t)sidx[t] * DD + j];
        __syncthreads();
    }
    agg[(size_t)node * DD + j] = acc + (a0 + a1) + (a2 + a3);
}

// ---------------------------------------------------------------------------
// MLP: out[n] = act( hin[n] @ W + b ).  W staged in shared, 8 nodes per pass
// (32 FMA per 12 LDS in the k-quad inner step).
// MODE 0: ReLU.  MODE 1: log_softmax over the 128 columns.
// ---------------------------------------------------------------------------
#define NPB 16
#define INP 8   // nodes per inner pass

template <int MODE>
__global__ void mlp_kernel(const float* __restrict__ hin,
                           const float* __restrict__ W,
                           const float* __restrict__ b,
                           float* __restrict__ out) {
    extern __shared__ float sm[];
    float* sW   = sm;              // 128*128
    float* srow = sm + DD * DD;    // INP*128
    __shared__ float sred[INP * 4];

    int j = threadIdx.x;  // 0..127
    int lane = j & 31, wid = j >> 5;

    for (int i = j; i < DD * DD / 4; i += blockDim.x)
        ((float4*)sW)[i] = ((const float4*)W)[i];
    float bj = b[j];
    __syncthreads();

    int base = blockIdx.x * NPB;
    for (int n0 = 0; n0 < NPB; n0 += INP) {
        int node = base + n0;
#pragma unroll
        for (int t = 0; t < INP; t++) {
            int n = node + t;
            srow[t * DD + j] = (n < NN) ? hin[(size_t)n * DD + j] : 0.f;
        }
        __syncthreads();

        float acc[INP];
#pragma unroll
        for (int t = 0; t < INP; t++) acc[t] = bj;

#pragma unroll 4
        for (int k = 0; k < DD; k += 4) {
            float w0 = sW[(k + 0) * DD + j];
            float w1 = sW[(k + 1) * DD + j];
            float w2 = sW[(k + 2) * DD + j];
            float w3 = sW[(k + 3) * DD + j];
#pragma unroll
            for (int t = 0; t < INP; t++) {
                float4 r = *(const float4*)&srow[t * DD + k];
                acc[t] = fmaf(r.x, w0, acc[t]);
                acc[t] = fmaf(r.y, w1, acc[t]);
                acc[t] = fmaf(r.z, w2, acc[t]);
                acc[t] = fmaf(r.w, w3, acc[t]);
            }
        }

        if (MODE == 0) {
#pragma unroll
            for (int t = 0; t < INP; t++) {
                int n = node + t;
                if (n < NN) out[(size_t)n * DD + j] = fmaxf(acc[t], 0.f);
            }
        } else {
            float m[INP], s[INP];
#pragma unroll
            for (int t = 0; t < INP; t++) {
                float mm = acc[t];
#pragma unroll
                for (int o = 16; o; o >>= 1)
                    mm = fmaxf(mm, __shfl_xor_sync(0xffffffffu, mm, o));
                if (lane == 0) sred[t * 4 + wid] = mm;
            }
            __syncthreads();
#pragma unroll
            for (int t = 0; t < INP; t++)
                m[t] = fmaxf(fmaxf(sred[t * 4 + 0], sred[t * 4 + 1]),
                             fmaxf(sred[t * 4 + 2], sred[t * 4 + 3]));
            __syncthreads();
#pragma unroll
            for (int t = 0; t < INP; t++) {
                float ss = expf(acc[t] - m[t]);
#pragma unroll
                for (int o = 16; o; o >>= 1)
                    ss += __shfl_xor_sync(0xffffffffu, ss, o);
                if (lane == 0) sred[t * 4 + wid] = ss;
            }
            __syncthreads();
#pragma unroll
            for (int t = 0; t < INP; t++)
                s[t] = (sred[t * 4 + 0] + sred[t * 4 + 1]) +
                       (sred[t * 4 + 2] + sred[t * 4 + 3]);
#pragma unroll
            for (int t = 0; t < INP; t++) {
                int n = node + t;
                if (n < NN) out[(size_t)n * DD + j] = acc[t] - m[t] - logf(s[t]);
            }
        }
        __syncthreads();
    }
}

extern "C" void kernel_launch(void* const* d_in, const int* in_sizes, int n_in,
                              void* d_out, int out_size) {
    const float* x   = (const float*)d_in[0];
    const void*  ei  = d_in[1];
    const float* w1  = (const float*)d_in[2];
    const float* b1  = (const float*)d_in[3];
    const float* w2  = (const float*)d_in[4];
    const float* b2  = (const float*)d_in[5];
    float* out       = (float*)d_out;
    int E = in_sizes[1] / 2;
    if (E > EMAX) E = EMAX;

    float* agg = nullptr;
    float* h1  = nullptr;
    cudaGetSymbolAddress((void**)&agg, g_agg);
    cudaGetSymbolAddress((void**)&h1,  g_h1);

    const int SMEM = (DD * DD + INP * DD) * (int)sizeof(float);  // 69632 B
    cudaFuncSetAttribute(mlp_kernel<0>, cudaFuncAttributeMaxDynamicSharedMemorySize, SMEM);
    cudaFuncSetAttribute(mlp_kernel<1>, cudaFuncAttributeMaxDynamicSharedMemorySize, SMEM);

    const int eb4 = (E / 4 + 255) / 256;
    const int mlp_blocks = (NN + NPB - 1) / NPB;

    // ---- CSR build (once, reused by both layers) ----
    init_kernel<<<(NN + 255) / 256, 256>>>(ei);
    hist_kernel<<<eb4, 256>>>(ei, E);
    scan_kernel<<<1, 1024>>>();
    fill_kernel<<<eb4, 256>>>(ei, E);

    // ---- layer 1 ----
    agg_gather_kernel<<<NN, 128>>>(x, agg);
    mlp_kernel<0><<<mlp_blocks, 128, SMEM>>>(agg, w1, b1, h1);

    // ---- layer 2 ----
    agg_gather_kernel<<<NN, 128>>>(h1, agg);
    mlp_kernel<1><<<mlp_blocks, 128, SMEM>>>(agg, w2, b2, out);
}